// round 3
// baseline (speedup 1.0000x reference)
#include <cuda_runtime.h>
#include <cuda_bf16.h>
#include <cstdint>
#include <cstddef>

// ---------------- problem constants ----------------
#define NA      100000          // atoms
#define MN      12              // neighbors
#define AF      64              // atom feature len
#define NFE     41              // nbr feature len
#define C2      128             // 2*AF
#define NMROWS  (NA*MN)         // 1,200,000 edge rows
#define NB_B    (NMROWS/64)     // 18750 blocks in gemm pass
#define NB_C    (NA/16)         // 6250 blocks in apply pass
#define N0C     100             // crystals
#define APC     1000            // atoms per crystal
#define HFD     128
#define HIDD    64
#define EPSV    1e-5f

// ---------------- device scratch (no allocations allowed) ----------------
__device__ float g_atom  [NA*AF];            // 25.6 MB
__device__ float g_Pself [NA*C2];            // 51.2 MB
__device__ float g_Pnbr  [NA*C2];            // 51.2 MB
__device__ float g_gated [(size_t)NMROWS*C2];// 614.4 MB
__device__ float g_summed[NA*AF];            // 25.6 MB
__device__ float g_part1 [256*NB_B];         // per-block bn1 partials [col][blk]
__device__ float g_part2 [128*NB_C];         // per-block bn2 partials [col][blk]
__device__ float g_red1  [256];
__device__ float g_red2  [128];
__device__ float g_sc1[128], g_sh1[128];
__device__ float g_sc2[64],  g_sh2[64];

// ---------------- helpers ----------------
__device__ __forceinline__ float softplusf(float x) {
    return fmaxf(x, 0.f) + log1pf(__expf(-fabsf(x)));
}
__device__ __forceinline__ float sigmoidf_(float x) {
    return 1.f / (1.f + __expf(-x));
}

// ---------------- k_embed: atom_fea = embedding[atom_num] ----------------
__global__ __launch_bounds__(256) void k_embed(const int* __restrict__ atom_num,
                                               const float* __restrict__ emb) {
    int i = blockIdx.x * 256 + threadIdx.x;     // over NA*AF/4 = 1.6M
    int base = i * 4;
    int n = base >> 6;
    int c = base & 63;
    int a = atom_num[n];
    float4 v = *(const float4*)(emb + a * AF + c);
    *(float4*)(g_atom + base) = v;
}

// ---------------- k_A: [Pself | Pnbr] = atom_fea @ W[0:128,:] ----------------
// block: 64 rows x 256 cols, 256 threads (16 rowtiles x 16 coltiles), thread 4x16
#define A_SMEM_BYTES ((64*68 + 64*256) * 4)
__global__ __launch_bounds__(256) void k_A(const float* __restrict__ W) {
    extern __shared__ float sm[];
    float* sAT = sm;            // [64 k][68] transposed A tile (pad 4)
    float* sW  = sm + 64*68;    // [64 k][256] combined self|nbr weights
    int tid = threadIdx.x;
    int r0 = blockIdx.x * 64;

    for (int idx = tid; idx < 64*64; idx += 256) {
        int row = idx >> 6, k = idx & 63;
        int r = r0 + row;
        sAT[k*68 + row] = (r < NA) ? g_atom[r*AF + k] : 0.f;
    }
    for (int idx = tid; idx < 64*256; idx += 256) {
        int k = idx >> 8, cc = idx & 255;
        sW[idx] = (cc < 128) ? W[k*128 + cc] : W[(k + 64)*128 + (cc - 128)];
    }
    __syncthreads();

    int ct = tid & 15, rt = tid >> 4;
    float acc[4][16];
    #pragma unroll
    for (int i = 0; i < 4; i++)
        #pragma unroll
        for (int j = 0; j < 16; j++) acc[i][j] = 0.f;

    #pragma unroll 4
    for (int k = 0; k < 64; k++) {
        float4 a4 = *(const float4*)(sAT + k*68 + rt*4);
        const float* wr = sW + k*256 + ct*16;
        float4 w0 = *(const float4*)(wr);
        float4 w1 = *(const float4*)(wr + 4);
        float4 w2 = *(const float4*)(wr + 8);
        float4 w3 = *(const float4*)(wr + 12);
        float av[4] = {a4.x, a4.y, a4.z, a4.w};
        float wv[16] = {w0.x,w0.y,w0.z,w0.w, w1.x,w1.y,w1.z,w1.w,
                        w2.x,w2.y,w2.z,w2.w, w3.x,w3.y,w3.z,w3.w};
        #pragma unroll
        for (int i = 0; i < 4; i++)
            #pragma unroll
            for (int j = 0; j < 16; j++)
                acc[i][j] += av[i] * wv[j];
    }

    bool isSelf = (ct < 8);
    int cb = isSelf ? ct*16 : (ct - 8)*16;
    float* dst = isSelf ? g_Pself : g_Pnbr;
    #pragma unroll
    for (int i = 0; i < 4; i++) {
        int r = r0 + rt*4 + i;
        if (r < NA) {
            float* p = dst + r*C2 + cb;
            *(float4*)(p)      = make_float4(acc[i][0],  acc[i][1],  acc[i][2],  acc[i][3]);
            *(float4*)(p + 4)  = make_float4(acc[i][4],  acc[i][5],  acc[i][6],  acc[i][7]);
            *(float4*)(p + 8)  = make_float4(acc[i][8],  acc[i][9],  acc[i][10], acc[i][11]);
            *(float4*)(p + 12) = make_float4(acc[i][12], acc[i][13], acc[i][14], acc[i][15]);
        }
    }
}

// ---------------- k_B: edge GEMM + assemble gated + bn1 partial stats ----------------
// block: 64 edge-rows x 128 cols, 256 threads (16x16), thread 4x8
__global__ __launch_bounds__(256) void k_B(const float* __restrict__ nbrF,
                                           const int*   __restrict__ nidx,
                                           const float* __restrict__ Wnf,
                                           const float* __restrict__ bias) {
    __shared__ __align__(16) float sNT[41*68];    // [k][row] transposed nbr_fea tile
    __shared__ __align__(16) float sW [41*128];   // [k][c]
    __shared__ float sbuf[16*128];
    int tid = threadIdx.x;
    int r0 = blockIdx.x * 64;

    const float* src = nbrF + (size_t)r0 * NFE;   // 64 contiguous rows
    for (int idx = tid; idx < 64*41; idx += 256) {
        int row = idx / 41, k = idx - row*41;
        sNT[k*68 + row] = src[idx];
    }
    for (int idx = tid; idx < 41*128; idx += 256) sW[idx] = Wnf[idx];
    __syncthreads();

    int ct = tid & 15, rt = tid >> 4;
    int c0 = ct * 8;
    float acc[4][8];
    #pragma unroll
    for (int i = 0; i < 4; i++)
        #pragma unroll
        for (int j = 0; j < 8; j++) acc[i][j] = 0.f;

    #pragma unroll 1
    for (int k = 0; k < 41; k++) {
        float4 a4 = *(const float4*)(sNT + k*68 + rt*4);
        float4 w0 = *(const float4*)(sW + k*128 + c0);
        float4 w1 = *(const float4*)(sW + k*128 + c0 + 4);
        float av[4] = {a4.x, a4.y, a4.z, a4.w};
        float wv[8] = {w0.x,w0.y,w0.z,w0.w, w1.x,w1.y,w1.z,w1.w};
        #pragma unroll
        for (int i = 0; i < 4; i++)
            #pragma unroll
            for (int j = 0; j < 8; j++)
                acc[i][j] += av[i] * wv[j];
    }

    float4 bb0 = *(const float4*)(bias + c0);
    float4 bb1 = *(const float4*)(bias + c0 + 4);
    float ssum[8], ssq[8];
    #pragma unroll
    for (int j = 0; j < 8; j++) { ssum[j] = 0.f; ssq[j] = 0.f; }

    #pragma unroll
    for (int i = 0; i < 4; i++) {
        int r = r0 + rt*4 + i;
        int n = r / MN;
        int jn = nidx[r];
        const float4 p0 = *(const float4*)(g_Pself + n*C2 + c0);
        const float4 p1 = *(const float4*)(g_Pself + n*C2 + c0 + 4);
        const float4 q0 = *(const float4*)(g_Pnbr + jn*C2 + c0);
        const float4 q1 = *(const float4*)(g_Pnbr + jn*C2 + c0 + 4);
        float gv[8];
        gv[0] = acc[i][0] + p0.x + q0.x + bb0.x;
        gv[1] = acc[i][1] + p0.y + q0.y + bb0.y;
        gv[2] = acc[i][2] + p0.z + q0.z + bb0.z;
        gv[3] = acc[i][3] + p0.w + q0.w + bb0.w;
        gv[4] = acc[i][4] + p1.x + q1.x + bb1.x;
        gv[5] = acc[i][5] + p1.y + q1.y + bb1.y;
        gv[6] = acc[i][6] + p1.z + q1.z + bb1.z;
        gv[7] = acc[i][7] + p1.w + q1.w + bb1.w;
        float* gp = g_gated + (size_t)r * C2 + c0;
        *(float4*)(gp)     = make_float4(gv[0], gv[1], gv[2], gv[3]);
        *(float4*)(gp + 4) = make_float4(gv[4], gv[5], gv[6], gv[7]);
        #pragma unroll
        for (int j = 0; j < 8; j++) { ssum[j] += gv[j]; ssq[j] += gv[j]*gv[j]; }
    }

    // deterministic block reduction: 16 rowtiles -> 1, fixed order
    #pragma unroll
    for (int j = 0; j < 8; j++) sbuf[rt*128 + c0 + j] = ssum[j];
    __syncthreads();
    if (tid < 128) {
        float t = 0.f;
        #pragma unroll
        for (int q = 0; q < 16; q++) t += sbuf[q*128 + tid];
        g_part1[tid*NB_B + blockIdx.x] = t;
    }
    __syncthreads();
    #pragma unroll
    for (int j = 0; j < 8; j++) sbuf[rt*128 + c0 + j] = ssq[j];
    __syncthreads();
    if (tid < 128) {
        float t = 0.f;
        #pragma unroll
        for (int q = 0; q < 16; q++) t += sbuf[q*128 + tid];
        g_part1[(128 + tid)*NB_B + blockIdx.x] = t;
    }
}

// ---------------- k_redcol: deterministic per-column cross-block reduce ----------------
__global__ __launch_bounds__(256) void k_redcol(int which) {
    const float* part = which ? g_part2 : g_part1;
    float* out = which ? g_red2 : g_red1;
    int nb = which ? NB_C : NB_B;
    int c = blockIdx.x;
    const float* p = part + (size_t)c * nb;
    float a = 0.f;
    for (int i = threadIdx.x; i < nb; i += 256) a += p[i];
    __shared__ float sh[256];
    sh[threadIdx.x] = a;
    __syncthreads();
    for (int s = 128; s > 0; s >>= 1) {
        if (threadIdx.x < s) sh[threadIdx.x] += sh[threadIdx.x + s];
        __syncthreads();
    }
    if (threadIdx.x == 0) out[c] = sh[0];
}

// ---------------- bn finalize ----------------
__global__ void k_fin1(const float* __restrict__ g1, const float* __restrict__ b1) {
    int c = threadIdx.x;   // 128
    const float invn = 1.f / (float)NMROWS;
    float mu  = g_red1[c] * invn;
    float var = g_red1[128 + c] * invn - mu*mu;
    float is  = rsqrtf(var + EPSV);
    float sc  = g1[c] * is;
    g_sc1[c] = sc;
    g_sh1[c] = b1[c] - mu * sc;
}
__global__ void k_fin2(const float* __restrict__ g2, const float* __restrict__ b2) {
    int c = threadIdx.x;   // 64
    const float invn = 1.f / (float)NA;
    float mu  = g_red2[c] * invn;
    float var = g_red2[64 + c] * invn - mu*mu;
    float is  = rsqrtf(var + EPSV);
    float sc  = g2[c] * is;
    g_sc2[c] = sc;
    g_sh2[c] = b2[c] - mu * sc;
}

// ---------------- k_C: BN1 + sigmoid*softplus + sum over m + bn2 partials ----------------
// block: 16 atoms, 256 threads (4 atom-groups x 64 features)
__global__ __launch_bounds__(256) void k_C() {
    int tid = threadIdx.x;
    int f = tid & 63, ag = tid >> 6;
    int n0 = blockIdx.x * 16;
    float sc0 = g_sc1[f],      sh0 = g_sh1[f];
    float sc1 = g_sc1[64 + f], sh1 = g_sh1[64 + f];
    float ps = 0.f, pq = 0.f;
    __shared__ float st[512];
    #pragma unroll
    for (int aa = 0; aa < 4; aa++) {
        int n = n0 + ag*4 + aa;
        const float* gp = g_gated + (size_t)n * MN * C2;
        float s = 0.f;
        #pragma unroll
        for (int m = 0; m < MN; m++) {
            float y0 = gp[m*C2 + f]      * sc0 + sh0;
            float y1 = gp[m*C2 + 64 + f] * sc1 + sh1;
            s += sigmoidf_(y0) * softplusf(y1);
        }
        g_summed[n*AF + f] = s;
        ps += s; pq += s*s;
    }
    st[ag*64 + f] = ps;
    st[256 + ag*64 + f] = pq;
    __syncthreads();
    if (tid < 128) {
        int w = tid >> 6, f2 = tid & 63;
        float t = 0.f;
        #pragma unroll
        for (int q = 0; q < 4; q++) t += st[w*256 + q*64 + f2];
        g_part2[(w*64 + f2)*NB_C + blockIdx.x] = t;
    }
}

// ---------------- k_update: atom = softplus(atom + bn2(summed)) ----------------
__global__ __launch_bounds__(256) void k_update() {
    int i = blockIdx.x * 256 + threadIdx.x;
    int base = i * 4;
    int c = base & 63;
    float4 a = *(const float4*)(g_atom + base);
    float4 s = *(const float4*)(g_summed + base);
    float4 sc = *(const float4*)(g_sc2 + c);
    float4 sh = *(const float4*)(g_sh2 + c);
    float4 o;
    o.x = softplusf(a.x + s.x*sc.x + sh.x);
    o.y = softplusf(a.y + s.y*sc.y + sh.y);
    o.z = softplusf(a.z + s.z*sc.z + sh.z);
    o.w = softplusf(a.w + s.w*sc.w + sh.w);
    *(float4*)(g_atom + base) = o;
}

// ---------------- k_head: pooling + softplus + FC + softplus + out ----------------
__global__ __launch_bounds__(128) void k_head(const int* __restrict__ cidx,
                                              const float* __restrict__ Wfc,
                                              const float* __restrict__ bfc,
                                              const float* __restrict__ Wout,
                                              const float* __restrict__ bout,
                                              float* __restrict__ out) {
    __shared__ float s_c[64];
    __shared__ float s_h[128];
    __shared__ float s_red[128];
    int b = blockIdx.x, t = threadIdx.x;
    int f = t & 63, half = t >> 6;
    const int* ci = cidx + b * APC;
    float acc = 0.f;
    for (int a = half*500; a < half*500 + 500; a++)
        acc += g_atom[ci[a]*AF + f];
    s_red[t] = acc;
    __syncthreads();
    if (t < 64) {
        float m = (s_red[t] + s_red[t + 64]) * (1.f / (float)APC);
        s_c[t] = softplusf(m);
    }
    __syncthreads();
    {   // fc: h = t
        float a2 = bfc[t];
        #pragma unroll 8
        for (int f2 = 0; f2 < 64; f2++) a2 += s_c[f2] * Wfc[f2*HFD + t];
        s_h[t] = softplusf(a2);
    }
    __syncthreads();
    if (t < 64) {
        float a3 = bout[t];
        #pragma unroll 8
        for (int h = 0; h < 128; h++) a3 += s_h[h] * Wout[h*HIDD + t];
        out[b*HIDD + t] = a3;
    }
}

// ---------------- launch ----------------
extern "C" void kernel_launch(void* const* d_in, const int* in_sizes, int n_in,
                              void* d_out, int out_size) {
    const int*   atom_num = (const int*)  d_in[0];
    const float* nbr_fea  = (const float*)d_in[1];
    const int*   nbr_idx  = (const int*)  d_in[2];
    const int*   cidx     = (const int*)  d_in[3];
    const float* emb      = (const float*)d_in[4];
    const float* W_full   = (const float*)d_in[5];
    const float* b_full   = (const float*)d_in[6];
    const float* bn1g     = (const float*)d_in[7];
    const float* bn1b     = (const float*)d_in[8];
    const float* bn2g     = (const float*)d_in[9];
    const float* bn2b     = (const float*)d_in[10];
    const float* W_fc     = (const float*)d_in[11];
    const float* b_fc     = (const float*)d_in[12];
    const float* W_out    = (const float*)d_in[13];
    const float* b_out    = (const float*)d_in[14];
    float* out = (float*)d_out;

    cudaFuncSetAttribute(k_A, cudaFuncAttributeMaxDynamicSharedMemorySize, A_SMEM_BYTES);

    k_embed<<<NA*AF/1024, 256>>>(atom_num, emb);

    for (int l = 0; l < 3; l++) {
        const float* W = W_full + l * 169 * 128;
        k_A<<<(NA + 63)/64, 256, A_SMEM_BYTES>>>(W);
        k_B<<<NB_B, 256>>>(nbr_fea, nbr_idx, W + 128*128, b_full + l*128);
        k_redcol<<<256, 256>>>(0);
        k_fin1<<<1, 128>>>(bn1g + l*128, bn1b + l*128);
        k_C<<<NB_C, 256>>>();
        k_redcol<<<128, 256>>>(1);
        k_fin2<<<1, 64>>>(bn2g + l*64, bn2b + l*64);
        k_update<<<NA*AF/1024, 256>>>();
    }
    k_head<<<N0C, 128>>>(cidx, W_fc, b_fc, W_out, b_out, out);
}

// round 6
// speedup vs baseline: 1.0473x; 1.0473x over previous
#include <cuda_runtime.h>
#include <cuda_bf16.h>
#include <cstdint>
#include <cstddef>

// ---------------- problem constants ----------------
#define NA      100000          // atoms
#define MN      12              // neighbors
#define AF      64              // atom feature len
#define NFE     41              // nbr feature len
#define C2      128             // 2*AF
#define NMROWS  (NA*MN)         // 1,200,000 edge rows
#define NB_B    (NMROWS/64)     // 18750 blocks in gemm pass
#define NB_C    (NA/16)         // 6250 blocks in apply pass
#define N0C     100             // crystals
#define APC     1000            // atoms per crystal
#define HFD     128
#define HIDD    64
#define EPSV    1e-5f

typedef unsigned long long ull;

// ---------------- device scratch (no allocations allowed) ----------------
__device__ float g_atom  [NA*AF];
__device__ float g_Pself [NA*C2];
__device__ float g_Pnbr  [NA*C2];
__device__ float g_gated [(size_t)NMROWS*C2];
__device__ float g_summed[NA*AF];
__device__ float g_part1 [256*NB_B];
__device__ float g_part2 [128*NB_C];
__device__ float g_red1  [256];
__device__ float g_red2  [128];
__device__ float g_sc1[128], g_sh1[128];
__device__ float g_sc2[64],  g_sh2[64];

// ---------------- helpers ----------------
__device__ __forceinline__ float softplusf(float x) {
    return fmaxf(x, 0.f) + log1pf(__expf(-fabsf(x)));
}
__device__ __forceinline__ float sigmoidf_(float x) {
    return 1.f / (1.f + __expf(-x));
}
// packed f32x2 FMA: d = a*b + d  (two fp32 lanes per issue slot)
__device__ __forceinline__ void ffma2(ull& d, ull a, ull b) {
    asm("fma.rn.f32x2 %0, %1, %2, %0;" : "+l"(d) : "l"(a), "l"(b));
}
__device__ __forceinline__ ull dup2(float v) {
    unsigned int u = __float_as_uint(v);
    ull r;
    asm("mov.b64 %0, {%1, %1};" : "=l"(r) : "r"(u));
    return r;
}
__device__ __forceinline__ float2 lo2(const ull& v) {
    return *reinterpret_cast<const float2*>(&v);
}

// ---------------- k_embed ----------------
__global__ __launch_bounds__(256) void k_embed(const int* __restrict__ atom_num,
                                               const float* __restrict__ emb) {
    int i = blockIdx.x * 256 + threadIdx.x;
    int base = i * 4;
    int n = base >> 6;
    int c = base & 63;
    int a = atom_num[n];
    float4 v = *(const float4*)(emb + a * AF + c);
    *(float4*)(g_atom + base) = v;
}

// ---------------- k_A: [Pself | Pnbr] = atom_fea @ W[0:128,:] ----------------
// block: 64 rows x 256 cols, 256 threads (16 rowtiles x 16 coltiles), thread 4x16
// A operand duplicated in smem as {v,v} pairs -> pure LDS+FFMA2 inner loop
#define A_SMEM_BYTES (64*68*8 + 64*256*4)     // dupA 34816 + W 65536 = 100352
__global__ __launch_bounds__(256) void k_A(const float* __restrict__ W) {
    extern __shared__ unsigned char smraw[];
    ull*   sA2 = (ull*)smraw;                 // [64 k][68 rows] duplicated pairs
    float* sW  = (float*)(smraw + 64*68*8);   // [64 k][256 cols]
    int tid = threadIdx.x;
    int r0 = blockIdx.x * 64;

    for (int idx = tid; idx < 64*64; idx += 256) {
        int row = idx >> 6, k = idx & 63;
        int r = r0 + row;
        float v = (r < NA) ? g_atom[r*AF + k] : 0.f;
        sA2[k*68 + row] = dup2(v);
    }
    for (int idx = tid; idx < 64*256; idx += 256) {
        int k = idx >> 8, cc = idx & 255;
        sW[idx] = (cc < 128) ? W[k*128 + cc] : W[(k + 64)*128 + (cc - 128)];
    }
    __syncthreads();

    int ct = tid & 15, rt = tid >> 4;
    int c0 = ct * 16;
    ull acc[4][8];
    #pragma unroll
    for (int i = 0; i < 4; i++)
        #pragma unroll
        for (int j = 0; j < 8; j++) acc[i][j] = 0ULL;

    #pragma unroll 1
    for (int k = 0; k < 64; k++) {
        const ulonglong2* ar = (const ulonglong2*)(sA2 + k*68 + rt*4);
        ulonglong2 a01 = ar[0], a23 = ar[1];
        const ulonglong2* wr = (const ulonglong2*)(sW + k*256 + c0);
        ulonglong2 w0 = wr[0], w1 = wr[1], w2 = wr[2], w3 = wr[3];
        ull av[4] = {a01.x, a01.y, a23.x, a23.y};
        ull wv[8] = {w0.x, w0.y, w1.x, w1.y, w2.x, w2.y, w3.x, w3.y};
        #pragma unroll
        for (int i = 0; i < 4; i++)
            #pragma unroll
            for (int j = 0; j < 8; j++)
                ffma2(acc[i][j], av[i], wv[j]);
    }

    bool isSelf = (ct < 8);
    int cb = isSelf ? ct*16 : (ct - 8)*16;
    float* dst = isSelf ? g_Pself : g_Pnbr;
    #pragma unroll
    for (int i = 0; i < 4; i++) {
        int r = r0 + rt*4 + i;
        if (r < NA) {
            float* p = dst + r*C2 + cb;
            float2 f0 = lo2(acc[i][0]), f1 = lo2(acc[i][1]);
            float2 f2 = lo2(acc[i][2]), f3 = lo2(acc[i][3]);
            float2 f4 = lo2(acc[i][4]), f5 = lo2(acc[i][5]);
            float2 f6 = lo2(acc[i][6]), f7 = lo2(acc[i][7]);
            *(float4*)(p)      = make_float4(f0.x, f0.y, f1.x, f1.y);
            *(float4*)(p + 4)  = make_float4(f2.x, f2.y, f3.x, f3.y);
            *(float4*)(p + 8)  = make_float4(f4.x, f4.y, f5.x, f5.y);
            *(float4*)(p + 12) = make_float4(f6.x, f6.y, f7.x, f7.y);
        }
    }
}

// ---------------- k_B: edge GEMM + assemble gated + bn1 partial stats ----------------
// block: 64 edge-rows x 128 cols, 256 threads (16x16), thread 4x8, FFMA2 packed
#define B_SMEM_BYTES (41*68*8 + 41*128*4 + 16*128*4)   // 22304 + 20992 + 8192 = 51488
__global__ __launch_bounds__(256) void k_B(const float* __restrict__ nbrF,
                                           const int*   __restrict__ nidx,
                                           const float* __restrict__ Wnf,
                                           const float* __restrict__ bias) {
    extern __shared__ unsigned char smraw[];
    ull*   sA2  = (ull*)smraw;                               // [41 k][68 rows] dup pairs
    float* sW   = (float*)(smraw + 41*68*8);                 // [41 k][128 c]
    float* sbuf = (float*)(smraw + 41*68*8 + 41*128*4);      // [16][128]
    int tid = threadIdx.x;
    int r0 = blockIdx.x * 64;

    const float* src = nbrF + (size_t)r0 * NFE;   // 64 contiguous rows
    for (int idx = tid; idx < 64*41; idx += 256) {
        int row = idx / 41, k = idx - row*41;
        sA2[k*68 + row] = dup2(src[idx]);
    }
    for (int idx = tid; idx < 41*128; idx += 256) sW[idx] = Wnf[idx];
    __syncthreads();

    int ct = tid & 15, rt = tid >> 4;
    int c0 = ct * 8;
    ull acc[4][4];
    #pragma unroll
    for (int i = 0; i < 4; i++)
        #pragma unroll
        for (int j = 0; j < 4; j++) acc[i][j] = 0ULL;

    #pragma unroll 1
    for (int k = 0; k < 41; k++) {
        const ulonglong2* ar = (const ulonglong2*)(sA2 + k*68 + rt*4);
        ulonglong2 a01 = ar[0], a23 = ar[1];
        const ulonglong2* wr = (const ulonglong2*)(sW + k*128 + c0);
        ulonglong2 w01 = wr[0], w23 = wr[1];
        ull av[4] = {a01.x, a01.y, a23.x, a23.y};
        ull wv[4] = {w01.x, w01.y, w23.x, w23.y};
        #pragma unroll
        for (int i = 0; i < 4; i++)
            #pragma unroll
            for (int j = 0; j < 4; j++)
                ffma2(acc[i][j], av[i], wv[j]);
    }

    float4 bb0 = *(const float4*)(bias + c0);
    float4 bb1 = *(const float4*)(bias + c0 + 4);
    float ssum[8], ssq[8];
    #pragma unroll
    for (int j = 0; j < 8; j++) { ssum[j] = 0.f; ssq[j] = 0.f; }

    #pragma unroll
    for (int i = 0; i < 4; i++) {
        int r = r0 + rt*4 + i;
        int n = r / MN;
        int jn = nidx[r];
        const float4 p0 = *(const float4*)(g_Pself + n*C2 + c0);
        const float4 p1 = *(const float4*)(g_Pself + n*C2 + c0 + 4);
        const float4 q0 = *(const float4*)(g_Pnbr + jn*C2 + c0);
        const float4 q1 = *(const float4*)(g_Pnbr + jn*C2 + c0 + 4);
        float2 a0 = lo2(acc[i][0]), a1 = lo2(acc[i][1]);
        float2 a2 = lo2(acc[i][2]), a3 = lo2(acc[i][3]);
        float gv[8];
        gv[0] = a0.x + p0.x + q0.x + bb0.x;
        gv[1] = a0.y + p0.y + q0.y + bb0.y;
        gv[2] = a1.x + p0.z + q0.z + bb0.z;
        gv[3] = a1.y + p0.w + q0.w + bb0.w;
        gv[4] = a2.x + p1.x + q1.x + bb1.x;
        gv[5] = a2.y + p1.y + q1.y + bb1.y;
        gv[6] = a3.x + p1.z + q1.z + bb1.z;
        gv[7] = a3.y + p1.w + q1.w + bb1.w;
        float* gp = g_gated + (size_t)r * C2 + c0;
        *(float4*)(gp)     = make_float4(gv[0], gv[1], gv[2], gv[3]);
        *(float4*)(gp + 4) = make_float4(gv[4], gv[5], gv[6], gv[7]);
        #pragma unroll
        for (int j = 0; j < 8; j++) { ssum[j] += gv[j]; ssq[j] += gv[j]*gv[j]; }
    }

    // deterministic block reduction: 16 rowtiles -> 1, fixed order
    #pragma unroll
    for (int j = 0; j < 8; j++) sbuf[rt*128 + c0 + j] = ssum[j];
    __syncthreads();
    if (tid < 128) {
        float t = 0.f;
        #pragma unroll
        for (int q = 0; q < 16; q++) t += sbuf[q*128 + tid];
        g_part1[tid*NB_B + blockIdx.x] = t;
    }
    __syncthreads();
    #pragma unroll
    for (int j = 0; j < 8; j++) sbuf[rt*128 + c0 + j] = ssq[j];
    __syncthreads();
    if (tid < 128) {
        float t = 0.f;
        #pragma unroll
        for (int q = 0; q < 16; q++) t += sbuf[q*128 + tid];
        g_part1[(128 + tid)*NB_B + blockIdx.x] = t;
    }
}

// ---------------- k_redcol: deterministic per-column cross-block reduce ----------------
__global__ __launch_bounds__(256) void k_redcol(int which) {
    const float* part = which ? g_part2 : g_part1;
    float* out = which ? g_red2 : g_red1;
    int nb = which ? NB_C : NB_B;
    int c = blockIdx.x;
    const float* p = part + (size_t)c * nb;
    float a = 0.f;
    for (int i = threadIdx.x; i < nb; i += 256) a += p[i];
    __shared__ float sh[256];
    sh[threadIdx.x] = a;
    __syncthreads();
    for (int s = 128; s > 0; s >>= 1) {
        if (threadIdx.x < s) sh[threadIdx.x] += sh[threadIdx.x + s];
        __syncthreads();
    }
    if (threadIdx.x == 0) out[c] = sh[0];
}

// ---------------- bn finalize ----------------
__global__ void k_fin1(const float* __restrict__ g1, const float* __restrict__ b1) {
    int c = threadIdx.x;   // 128
    const float invn = 1.f / (float)NMROWS;
    float mu  = g_red1[c] * invn;
    float var = g_red1[128 + c] * invn - mu*mu;
    float is  = rsqrtf(var + EPSV);
    float sc  = g1[c] * is;
    g_sc1[c] = sc;
    g_sh1[c] = b1[c] - mu * sc;
}
__global__ void k_fin2(const float* __restrict__ g2, const float* __restrict__ b2) {
    int c = threadIdx.x;   // 64
    const float invn = 1.f / (float)NA;
    float mu  = g_red2[c] * invn;
    float var = g_red2[64 + c] * invn - mu*mu;
    float is  = rsqrtf(var + EPSV);
    float sc  = g2[c] * is;
    g_sc2[c] = sc;
    g_sh2[c] = b2[c] - mu * sc;
}

// ---------------- k_C: BN1 + sigmoid*softplus + sum over m + bn2 partials ----------------
__global__ __launch_bounds__(256) void k_C() {
    int tid = threadIdx.x;
    int f = tid & 63, ag = tid >> 6;
    int n0 = blockIdx.x * 16;
    float sc0 = g_sc1[f],      sh0 = g_sh1[f];
    float sc1 = g_sc1[64 + f], sh1 = g_sh1[64 + f];
    float ps = 0.f, pq = 0.f;
    __shared__ float st[512];
    #pragma unroll
    for (int aa = 0; aa < 4; aa++) {
        int n = n0 + ag*4 + aa;
        const float* gp = g_gated + (size_t)n * MN * C2;
        float s = 0.f;
        #pragma unroll
        for (int m = 0; m < MN; m++) {
            float y0 = gp[m*C2 + f]      * sc0 + sh0;
            float y1 = gp[m*C2 + 64 + f] * sc1 + sh1;
            s += sigmoidf_(y0) * softplusf(y1);
        }
        g_summed[n*AF + f] = s;
        ps += s; pq += s*s;
    }
    st[ag*64 + f] = ps;
    st[256 + ag*64 + f] = pq;
    __syncthreads();
    if (tid < 128) {
        int w = tid >> 6, f2 = tid & 63;
        float t = 0.f;
        #pragma unroll
        for (int q = 0; q < 4; q++) t += st[w*256 + q*64 + f2];
        g_part2[(w*64 + f2)*NB_C + blockIdx.x] = t;
    }
}

// ---------------- k_update: atom = softplus(atom + bn2(summed)) ----------------
__global__ __launch_bounds__(256) void k_update() {
    int i = blockIdx.x * 256 + threadIdx.x;
    int base = i * 4;
    int c = base & 63;
    float4 a = *(const float4*)(g_atom + base);
    float4 s = *(const float4*)(g_summed + base);
    float4 sc = *(const float4*)(g_sc2 + c);
    float4 sh = *(const float4*)(g_sh2 + c);
    float4 o;
    o.x = softplusf(a.x + s.x*sc.x + sh.x);
    o.y = softplusf(a.y + s.y*sc.y + sh.y);
    o.z = softplusf(a.z + s.z*sc.z + sh.z);
    o.w = softplusf(a.w + s.w*sc.w + sh.w);
    *(float4*)(g_atom + base) = o;
}

// ---------------- k_head: pooling + softplus + FC + softplus + out ----------------
__global__ __launch_bounds__(128) void k_head(const int* __restrict__ cidx,
                                              const float* __restrict__ Wfc,
                                              const float* __restrict__ bfc,
                                              const float* __restrict__ Wout,
                                              const float* __restrict__ bout,
                                              float* __restrict__ out) {
    __shared__ float s_c[64];
    __shared__ float s_h[128];
    __shared__ float s_red[128];
    int b = blockIdx.x, t = threadIdx.x;
    int f = t & 63, half = t >> 6;
    const int* ci = cidx + b * APC;
    float acc = 0.f;
    for (int a = half*500; a < half*500 + 500; a++)
        acc += g_atom[ci[a]*AF + f];
    s_red[t] = acc;
    __syncthreads();
    if (t < 64) {
        float m = (s_red[t] + s_red[t + 64]) * (1.f / (float)APC);
        s_c[t] = softplusf(m);
    }
    __syncthreads();
    {
        float a2 = bfc[t];
        #pragma unroll 8
        for (int f2 = 0; f2 < 64; f2++) a2 += s_c[f2] * Wfc[f2*HFD + t];
        s_h[t] = softplusf(a2);
    }
    __syncthreads();
    if (t < 64) {
        float a3 = bout[t];
        #pragma unroll 8
        for (int h = 0; h < 128; h++) a3 += s_h[h] * Wout[h*HIDD + t];
        out[b*HIDD + t] = a3;
    }
}

// ---------------- launch ----------------
extern "C" void kernel_launch(void* const* d_in, const int* in_sizes, int n_in,
                              void* d_out, int out_size) {
    const int*   atom_num = (const int*)  d_in[0];
    const float* nbr_fea  = (const float*)d_in[1];
    const int*   nbr_idx  = (const int*)  d_in[2];
    const int*   cidx     = (const int*)  d_in[3];
    const float* emb      = (const float*)d_in[4];
    const float* W_full   = (const float*)d_in[5];
    const float* b_full   = (const float*)d_in[6];
    const float* bn1g     = (const float*)d_in[7];
    const float* bn1b     = (const float*)d_in[8];
    const float* bn2g     = (const float*)d_in[9];
    const float* bn2b     = (const float*)d_in[10];
    const float* W_fc     = (const float*)d_in[11];
    const float* b_fc     = (const float*)d_in[12];
    const float* W_out    = (const float*)d_in[13];
    const float* b_out    = (const float*)d_in[14];
    float* out = (float*)d_out;

    cudaFuncSetAttribute(k_A, cudaFuncAttributeMaxDynamicSharedMemorySize, A_SMEM_BYTES);
    cudaFuncSetAttribute(k_B, cudaFuncAttributeMaxDynamicSharedMemorySize, B_SMEM_BYTES);

    k_embed<<<NA*AF/1024, 256>>>(atom_num, emb);

    for (int l = 0; l < 3; l++) {
        const float* W = W_full + l * 169 * 128;
        k_A<<<(NA + 63)/64, 256, A_SMEM_BYTES>>>(W);
        k_B<<<NB_B, 256, B_SMEM_BYTES>>>(nbr_fea, nbr_idx, W + 128*128, b_full + l*128);
        k_redcol<<<256, 256>>>(0);
        k_fin1<<<1, 128>>>(bn1g + l*128, bn1b + l*128);
        k_C<<<NB_C, 256>>>();
        k_redcol<<<128, 256>>>(1);
        k_fin2<<<1, 64>>>(bn2g + l*64, bn2b + l*64);
        k_update<<<NA*AF/1024, 256>>>();
    }
    k_head<<<N0C, 128>>>(cidx, W_fc, b_fc, W_out, b_out, out);
}

// round 10
// speedup vs baseline: 1.1168x; 1.0664x over previous
#include <cuda_runtime.h>
#include <cuda_fp16.h>
#include <cuda_bf16.h>
#include <cstdint>
#include <cstddef>

// ---------------- problem constants ----------------
#define NA      100000          // atoms
#define MN      12              // neighbors
#define AF      64              // atom feature len
#define NFE     41              // nbr feature len
#define C2      128             // 2*AF
#define NMROWS  (NA*MN)         // 1,200,000 edge rows
#define NB_B    (NMROWS/64)     // 18750 blocks in gemm pass
#define NB_C    (NA/16)         // 6250 blocks in apply pass
#define N0C     100             // crystals
#define APC     1000            // atoms per crystal
#define HFD     128
#define HIDD    64
#define EPSV    1e-5f
#define NBR_ELEMS (NMROWS*NFE)  // 49,200,000

typedef unsigned long long ull;

// ---------------- device scratch (no allocations allowed) ----------------
__device__ float  g_atom  [NA*AF];
__device__ float  g_Pself [NA*C2];
__device__ float  g_Pnbr  [NA*C2];
__device__ __half g_gatedh[(size_t)NMROWS*C2];   // 307 MB (was 614 MB fp32)
__device__ __half g_nbrh  [NBR_ELEMS];           // 98 MB fp16 copy of nbr_fea
__device__ float  g_summed[NA*AF];
__device__ float  g_part1 [256*NB_B];
__device__ float  g_part2 [128*NB_C];
__device__ float  g_red1  [256];
__device__ float  g_red2  [128];
__device__ float  g_sc1[128], g_sh1[128];
__device__ float  g_sc2[64],  g_sh2[64];

// ---------------- helpers ----------------
__device__ __forceinline__ float softplusf(float x) {
    return fmaxf(x, 0.f) + log1pf(__expf(-fabsf(x)));
}
__device__ __forceinline__ float sigmoidf_(float x) {
    return 1.f / (1.f + __expf(-x));
}
// packed f32x2 FMA: d = a*b + d  (two fp32 lanes per issue slot)
__device__ __forceinline__ void ffma2(ull& d, ull a, ull b) {
    asm("fma.rn.f32x2 %0, %1, %2, %0;" : "+l"(d) : "l"(a), "l"(b));
}
__device__ __forceinline__ ull dup2(float v) {
    unsigned int u = __float_as_uint(v);
    ull r;
    asm("mov.b64 %0, {%1, %1};" : "=l"(r) : "r"(u));
    return r;
}
__device__ __forceinline__ float2 lo2(const ull& v) {
    return *reinterpret_cast<const float2*>(&v);
}

// ---------------- k_embed ----------------
__global__ __launch_bounds__(256) void k_embed(const int* __restrict__ atom_num,
                                               const float* __restrict__ emb) {
    int i = blockIdx.x * 256 + threadIdx.x;
    int base = i * 4;
    int n = base >> 6;
    int c = base & 63;
    int a = atom_num[n];
    float4 v = *(const float4*)(emb + a * AF + c);
    *(float4*)(g_atom + base) = v;
}

// ---------------- k_prep: nbr_fea fp32 -> fp16 (once) ----------------
__global__ __launch_bounds__(256) void k_prep(const float* __restrict__ nbrF) {
    int i = blockIdx.x * 256 + threadIdx.x;
    int base = i * 4;
    if (base >= NBR_ELEMS) return;
    float4 v = *(const float4*)(nbrF + base);
    __half2 h0 = __floats2half2_rn(v.x, v.y);
    __half2 h1 = __floats2half2_rn(v.z, v.w);
    uint2 o;
    o.x = *(unsigned int*)&h0;
    o.y = *(unsigned int*)&h1;
    *(uint2*)(g_nbrh + base) = o;
}

// ---------------- k_A: [Pself | Pnbr] = atom_fea @ W[0:128,:] ----------------
// block: 64 rows x 256 cols, 256 threads (16 rowtiles x 16 coltiles), thread 4x16
#define A_SMEM_BYTES (64*68*8 + 64*256*4)     // dupA 34816 + W 65536 = 100352
__global__ __launch_bounds__(256) void k_A(const float* __restrict__ W) {
    extern __shared__ unsigned char smraw[];
    ull*   sA2 = (ull*)smraw;                 // [64 k][68 rows] duplicated pairs
    float* sW  = (float*)(smraw + 64*68*8);   // [64 k][256 cols]
    int tid = threadIdx.x;
    int r0 = blockIdx.x * 64;

    for (int idx = tid; idx < 64*64; idx += 256) {
        int row = idx >> 6, k = idx & 63;
        int r = r0 + row;
        float v = (r < NA) ? g_atom[r*AF + k] : 0.f;
        sA2[k*68 + row] = dup2(v);
    }
    for (int idx = tid; idx < 64*256; idx += 256) {
        int k = idx >> 8, cc = idx & 255;
        sW[idx] = (cc < 128) ? W[k*128 + cc] : W[(k + 64)*128 + (cc - 128)];
    }
    __syncthreads();

    int ct = tid & 15, rt = tid >> 4;
    int c0 = ct * 16;
    ull acc[4][8];
    #pragma unroll
    for (int i = 0; i < 4; i++)
        #pragma unroll
        for (int j = 0; j < 8; j++) acc[i][j] = 0ULL;

    #pragma unroll 1
    for (int k = 0; k < 64; k++) {
        const ulonglong2* ar = (const ulonglong2*)(sA2 + k*68 + rt*4);
        ulonglong2 a01 = ar[0], a23 = ar[1];
        const ulonglong2* wr = (const ulonglong2*)(sW + k*256 + c0);
        ulonglong2 w0 = wr[0], w1 = wr[1], w2 = wr[2], w3 = wr[3];
        ull av[4] = {a01.x, a01.y, a23.x, a23.y};
        ull wv[8] = {w0.x, w0.y, w1.x, w1.y, w2.x, w2.y, w3.x, w3.y};
        #pragma unroll
        for (int i = 0; i < 4; i++)
            #pragma unroll
            for (int j = 0; j < 8; j++)
                ffma2(acc[i][j], av[i], wv[j]);
    }

    bool isSelf = (ct < 8);
    int cb = isSelf ? ct*16 : (ct - 8)*16;
    float* dst = isSelf ? g_Pself : g_Pnbr;
    #pragma unroll
    for (int i = 0; i < 4; i++) {
        int r = r0 + rt*4 + i;
        if (r < NA) {
            float* p = dst + r*C2 + cb;
            float2 f0 = lo2(acc[i][0]), f1 = lo2(acc[i][1]);
            float2 f2 = lo2(acc[i][2]), f3 = lo2(acc[i][3]);
            float2 f4 = lo2(acc[i][4]), f5 = lo2(acc[i][5]);
            float2 f6 = lo2(acc[i][6]), f7 = lo2(acc[i][7]);
            *(float4*)(p)      = make_float4(f0.x, f0.y, f1.x, f1.y);
            *(float4*)(p + 4)  = make_float4(f2.x, f2.y, f3.x, f3.y);
            *(float4*)(p + 8)  = make_float4(f4.x, f4.y, f5.x, f5.y);
            *(float4*)(p + 12) = make_float4(f6.x, f6.y, f7.x, f7.y);
        }
    }
}

// ---------------- k_B: edge GEMM + assemble gated(fp16) + bn1 partial stats ----------------
// block: 64 edge-rows x 128 cols, 256 threads (16x16), thread 4x8, FFMA2 packed
#define B_SMEM_BYTES (41*68*8 + 41*128*4 + 16*128*4)   // 22304 + 20992 + 8192 = 51488
__global__ __launch_bounds__(256) void k_B(const int*   __restrict__ nidx,
                                           const float* __restrict__ Wnf,
                                           const float* __restrict__ bias) {
    extern __shared__ unsigned char smraw[];
    ull*   sA2  = (ull*)smraw;                               // [41 k][68 rows] dup pairs
    float* sW   = (float*)(smraw + 41*68*8);                 // [41 k][128 c]
    float* sbuf = (float*)(smraw + 41*68*8 + 41*128*4);      // [16][128]
    int tid = threadIdx.x;
    int r0 = blockIdx.x * 64;

    const __half* src = g_nbrh + (size_t)r0 * NFE;   // 64 contiguous rows
    for (int idx = tid; idx < 64*41; idx += 256) {
        int row = idx / 41, k = idx - row*41;
        sA2[k*68 + row] = dup2(__half2float(src[idx]));
    }
    for (int idx = tid; idx < 41*128; idx += 256) sW[idx] = Wnf[idx];
    __syncthreads();

    int ct = tid & 15, rt = tid >> 4;
    int c0 = ct * 8;
    ull acc[4][4];
    #pragma unroll
    for (int i = 0; i < 4; i++)
        #pragma unroll
        for (int j = 0; j < 4; j++) acc[i][j] = 0ULL;

    #pragma unroll 1
    for (int k = 0; k < 41; k++) {
        const ulonglong2* ar = (const ulonglong2*)(sA2 + k*68 + rt*4);
        ulonglong2 a01 = ar[0], a23 = ar[1];
        const ulonglong2* wr = (const ulonglong2*)(sW + k*128 + c0);
        ulonglong2 w01 = wr[0], w23 = wr[1];
        ull av[4] = {a01.x, a01.y, a23.x, a23.y};
        ull wv[4] = {w01.x, w01.y, w23.x, w23.y};
        #pragma unroll
        for (int i = 0; i < 4; i++)
            #pragma unroll
            for (int j = 0; j < 4; j++)
                ffma2(acc[i][j], av[i], wv[j]);
    }

    float4 bb0 = *(const float4*)(bias + c0);
    float4 bb1 = *(const float4*)(bias + c0 + 4);
    float ssum[8], ssq[8];
    #pragma unroll
    for (int j = 0; j < 8; j++) { ssum[j] = 0.f; ssq[j] = 0.f; }

    #pragma unroll
    for (int i = 0; i < 4; i++) {
        int r = r0 + rt*4 + i;
        int n = r / MN;
        int jn = nidx[r];
        const float4 p0 = *(const float4*)(g_Pself + n*C2 + c0);
        const float4 p1 = *(const float4*)(g_Pself + n*C2 + c0 + 4);
        const float4 q0 = *(const float4*)(g_Pnbr + jn*C2 + c0);
        const float4 q1 = *(const float4*)(g_Pnbr + jn*C2 + c0 + 4);
        float2 a0 = lo2(acc[i][0]), a1 = lo2(acc[i][1]);
        float2 a2 = lo2(acc[i][2]), a3 = lo2(acc[i][3]);
        float gv[8];
        gv[0] = a0.x + p0.x + q0.x + bb0.x;
        gv[1] = a0.y + p0.y + q0.y + bb0.y;
        gv[2] = a1.x + p0.z + q0.z + bb0.z;
        gv[3] = a1.y + p0.w + q0.w + bb0.w;
        gv[4] = a2.x + p1.x + q1.x + bb1.x;
        gv[5] = a2.y + p1.y + q1.y + bb1.y;
        gv[6] = a3.x + p1.z + q1.z + bb1.z;
        gv[7] = a3.y + p1.w + q1.w + bb1.w;
        // fp16 store: 8 halves = 16 bytes, one vector store
        __half2 h0 = __floats2half2_rn(gv[0], gv[1]);
        __half2 h1 = __floats2half2_rn(gv[2], gv[3]);
        __half2 h2 = __floats2half2_rn(gv[4], gv[5]);
        __half2 h3 = __floats2half2_rn(gv[6], gv[7]);
        uint4 pk;
        pk.x = *(unsigned int*)&h0;
        pk.y = *(unsigned int*)&h1;
        pk.z = *(unsigned int*)&h2;
        pk.w = *(unsigned int*)&h3;
        *(uint4*)(g_gatedh + (size_t)r * C2 + c0) = pk;
        #pragma unroll
        for (int j = 0; j < 8; j++) { ssum[j] += gv[j]; ssq[j] += gv[j]*gv[j]; }
    }

    // deterministic block reduction: 16 rowtiles -> 1, fixed order
    #pragma unroll
    for (int j = 0; j < 8; j++) sbuf[rt*128 + c0 + j] = ssum[j];
    __syncthreads();
    if (tid < 128) {
        float t = 0.f;
        #pragma unroll
        for (int q = 0; q < 16; q++) t += sbuf[q*128 + tid];
        g_part1[tid*NB_B + blockIdx.x] = t;
    }
    __syncthreads();
    #pragma unroll
    for (int j = 0; j < 8; j++) sbuf[rt*128 + c0 + j] = ssq[j];
    __syncthreads();
    if (tid < 128) {
        float t = 0.f;
        #pragma unroll
        for (int q = 0; q < 16; q++) t += sbuf[q*128 + tid];
        g_part1[(128 + tid)*NB_B + blockIdx.x] = t;
    }
}

// ---------------- k_redcol: deterministic per-column cross-block reduce ----------------
__global__ __launch_bounds__(256) void k_redcol(int which) {
    const float* part = which ? g_part2 : g_part1;
    float* out = which ? g_red2 : g_red1;
    int nb = which ? NB_C : NB_B;
    int c = blockIdx.x;
    const float* p = part + (size_t)c * nb;
    float a = 0.f;
    for (int i = threadIdx.x; i < nb; i += 256) a += p[i];
    __shared__ float sh[256];
    sh[threadIdx.x] = a;
    __syncthreads();
    for (int s = 128; s > 0; s >>= 1) {
        if (threadIdx.x < s) sh[threadIdx.x] += sh[threadIdx.x + s];
        __syncthreads();
    }
    if (threadIdx.x == 0) out[c] = sh[0];
}

// ---------------- bn finalize ----------------
__global__ void k_fin1(const float* __restrict__ g1, const float* __restrict__ b1) {
    int c = threadIdx.x;   // 128
    const float invn = 1.f / (float)NMROWS;
    float mu  = g_red1[c] * invn;
    float var = g_red1[128 + c] * invn - mu*mu;
    float is  = rsqrtf(var + EPSV);
    float sc  = g1[c] * is;
    g_sc1[c] = sc;
    g_sh1[c] = b1[c] - mu * sc;
}
__global__ void k_fin2(const float* __restrict__ g2, const float* __restrict__ b2) {
    int c = threadIdx.x;   // 64
    const float invn = 1.f / (float)NA;
    float mu  = g_red2[c] * invn;
    float var = g_red2[64 + c] * invn - mu*mu;
    float is  = rsqrtf(var + EPSV);
    float sc  = g2[c] * is;
    g_sc2[c] = sc;
    g_sh2[c] = b2[c] - mu * sc;
}

// ---------------- k_C: BN1 + sigmoid*softplus + sum over m + bn2 partials ----------------
__global__ __launch_bounds__(256) void k_C() {
    int tid = threadIdx.x;
    int f = tid & 63, ag = tid >> 6;
    int n0 = blockIdx.x * 16;
    float sc0 = g_sc1[f],      sh0 = g_sh1[f];
    float sc1 = g_sc1[64 + f], sh1 = g_sh1[64 + f];
    float ps = 0.f, pq = 0.f;
    __shared__ float st[512];
    #pragma unroll
    for (int aa = 0; aa < 4; aa++) {
        int n = n0 + ag*4 + aa;
        const __half* gp = g_gatedh + (size_t)n * MN * C2;
        float s = 0.f;
        #pragma unroll
        for (int m = 0; m < MN; m++) {
            float y0 = __half2float(gp[m*C2 + f])      * sc0 + sh0;
            float y1 = __half2float(gp[m*C2 + 64 + f]) * sc1 + sh1;
            s += sigmoidf_(y0) * softplusf(y1);
        }
        g_summed[n*AF + f] = s;
        ps += s; pq += s*s;
    }
    st[ag*64 + f] = ps;
    st[256 + ag*64 + f] = pq;
    __syncthreads();
    if (tid < 128) {
        int w = tid >> 6, f2 = tid & 63;
        float t = 0.f;
        #pragma unroll
        for (int q = 0; q < 4; q++) t += st[w*256 + q*64 + f2];
        g_part2[(w*64 + f2)*NB_C + blockIdx.x] = t;
    }
}

// ---------------- k_update: atom = softplus(atom + bn2(summed)) ----------------
__global__ __launch_bounds__(256) void k_update() {
    int i = blockIdx.x * 256 + threadIdx.x;
    int base = i * 4;
    int c = base & 63;
    float4 a = *(const float4*)(g_atom + base);
    float4 s = *(const float4*)(g_summed + base);
    float4 sc = *(const float4*)(g_sc2 + c);
    float4 sh = *(const float4*)(g_sh2 + c);
    float4 o;
    o.x = softplusf(a.x + s.x*sc.x + sh.x);
    o.y = softplusf(a.y + s.y*sc.y + sh.y);
    o.z = softplusf(a.z + s.z*sc.z + sh.z);
    o.w = softplusf(a.w + s.w*sc.w + sh.w);
    *(float4*)(g_atom + base) = o;
}

// ---------------- k_head: pooling + softplus + FC + softplus + out ----------------
__global__ __launch_bounds__(128) void k_head(const int* __restrict__ cidx,
                                              const float* __restrict__ Wfc,
                                              const float* __restrict__ bfc,
                                              const float* __restrict__ Wout,
                                              const float* __restrict__ bout,
                                              float* __restrict__ out) {
    __shared__ float s_c[64];
    __shared__ float s_h[128];
    __shared__ float s_red[128];
    int b = blockIdx.x, t = threadIdx.x;
    int f = t & 63, half = t >> 6;
    const int* ci = cidx + b * APC;
    float acc = 0.f;
    for (int a = half*500; a < half*500 + 500; a++)
        acc += g_atom[ci[a]*AF + f];
    s_red[t] = acc;
    __syncthreads();
    if (t < 64) {
        float m = (s_red[t] + s_red[t + 64]) * (1.f / (float)APC);
        s_c[t] = softplusf(m);
    }
    __syncthreads();
    {
        float a2 = bfc[t];
        #pragma unroll 8
        for (int f2 = 0; f2 < 64; f2++) a2 += s_c[f2] * Wfc[f2*HFD + t];
        s_h[t] = softplusf(a2);
    }
    __syncthreads();
    if (t < 64) {
        float a3 = bout[t];
        #pragma unroll 8
        for (int h = 0; h < 128; h++) a3 += s_h[h] * Wout[h*HIDD + t];
        out[b*HIDD + t] = a3;
    }
}

// ---------------- launch ----------------
extern "C" void kernel_launch(void* const* d_in, const int* in_sizes, int n_in,
                              void* d_out, int out_size) {
    const int*   atom_num = (const int*)  d_in[0];
    const float* nbr_fea  = (const float*)d_in[1];
    const int*   nbr_idx  = (const int*)  d_in[2];
    const int*   cidx     = (const int*)  d_in[3];
    const float* emb      = (const float*)d_in[4];
    const float* W_full   = (const float*)d_in[5];
    const float* b_full   = (const float*)d_in[6];
    const float* bn1g     = (const float*)d_in[7];
    const float* bn1b     = (const float*)d_in[8];
    const float* bn2g     = (const float*)d_in[9];
    const float* bn2b     = (const float*)d_in[10];
    const float* W_fc     = (const float*)d_in[11];
    const float* b_fc     = (const float*)d_in[12];
    const float* W_out    = (const float*)d_in[13];
    const float* b_out    = (const float*)d_in[14];
    float* out = (float*)d_out;

    cudaFuncSetAttribute(k_A, cudaFuncAttributeMaxDynamicSharedMemorySize, A_SMEM_BYTES);
    cudaFuncSetAttribute(k_B, cudaFuncAttributeMaxDynamicSharedMemorySize, B_SMEM_BYTES);

    k_embed<<<NA*AF/1024, 256>>>(atom_num, emb);
    k_prep<<<(NBR_ELEMS/4 + 255)/256, 256>>>(nbr_fea);

    for (int l = 0; l < 3; l++) {
        const float* W = W_full + l * 169 * 128;
        k_A<<<(NA + 63)/64, 256, A_SMEM_BYTES>>>(W);
        k_B<<<NB_B, 256, B_SMEM_BYTES>>>(nbr_idx, W + 128*128, b_full + l*128);
        k_redcol<<<256, 256>>>(0);
        k_fin1<<<1, 128>>>(bn1g + l*128, bn1b + l*128);
        k_C<<<NB_C, 256>>>();
        k_redcol<<<128, 256>>>(1);
        k_fin2<<<1, 64>>>(bn2g + l*64, bn2b + l*64);
        k_update<<<NA*AF/1024, 256>>>();
    }
    k_head<<<N0C, 128>>>(cidx, W_fc, b_fc, W_out, b_out, out);
}

// round 11
// speedup vs baseline: 1.2999x; 1.1639x over previous
#include <cuda_runtime.h>
#include <cuda_fp16.h>
#include <cuda_bf16.h>
#include <cstdint>
#include <cstddef>

// ---------------- problem constants ----------------
#define NA      100000          // atoms
#define MN      12              // neighbors
#define AF      64              // atom feature len
#define NFE     41              // nbr feature len
#define C2      128             // 2*AF
#define NMROWS  (NA*MN)         // 1,200,000 edge rows
#define NB_B2   (NMROWS/128)    // 9375 blocks in gemm pass (128 rows/block)
#define NB_C    (NA/16)         // 6250 blocks in apply pass
#define N0C     100             // crystals
#define APC     1000            // atoms per crystal
#define HFD     128
#define HIDD    64
#define EPSV    1e-5f
#define NBR_ELEMS (NMROWS*NFE)  // 49,200,000

typedef unsigned long long ull;

// ---------------- device scratch (no allocations allowed) ----------------
__device__ float  g_atom  [NA*AF];
__device__ float  g_Pself [NA*C2];
__device__ float  g_Pnbr  [NA*C2];
__device__ __half g_gatedh[(size_t)NMROWS*C2];   // 307 MB
__device__ __half g_nbrh  [NBR_ELEMS];           // 98 MB fp16 copy of nbr_fea
__device__ float  g_summed[NA*AF];
__device__ float  g_part1 [256*NB_B2];
__device__ float  g_part2 [128*NB_C];
__device__ float  g_red1  [256];
__device__ float  g_red2  [128];
__device__ float  g_sc1[128], g_sh1[128];
__device__ float  g_sc2[64],  g_sh2[64];

// ---------------- helpers ----------------
__device__ __forceinline__ float softplusf(float x) {
    return fmaxf(x, 0.f) + log1pf(__expf(-fabsf(x)));
}
__device__ __forceinline__ float sigmoidf_(float x) {
    return 1.f / (1.f + __expf(-x));
}
// packed f32x2 FMA: d = a*b + d  (two fp32 lanes per issue slot)
__device__ __forceinline__ void ffma2(ull& d, ull a, ull b) {
    asm("fma.rn.f32x2 %0, %1, %2, %0;" : "+l"(d) : "l"(a), "l"(b));
}
__device__ __forceinline__ ull dup2(float v) {
    unsigned int u = __float_as_uint(v);
    ull r;
    asm("mov.b64 %0, {%1, %1};" : "=l"(r) : "r"(u));
    return r;
}
__device__ __forceinline__ float2 lo2(const ull& v) {
    return *reinterpret_cast<const float2*>(&v);
}

// ---------------- k_embed ----------------
__global__ __launch_bounds__(256) void k_embed(const int* __restrict__ atom_num,
                                               const float* __restrict__ emb) {
    int i = blockIdx.x * 256 + threadIdx.x;
    int base = i * 4;
    int n = base >> 6;
    int c = base & 63;
    int a = atom_num[n];
    float4 v = *(const float4*)(emb + a * AF + c);
    *(float4*)(g_atom + base) = v;
}

// ---------------- k_prep: nbr_fea fp32 -> fp16 (once) ----------------
__global__ __launch_bounds__(256) void k_prep(const float* __restrict__ nbrF) {
    int i = blockIdx.x * 256 + threadIdx.x;
    int base = i * 4;
    if (base >= NBR_ELEMS) return;
    float4 v = *(const float4*)(nbrF + base);
    __half2 h0 = __floats2half2_rn(v.x, v.y);
    __half2 h1 = __floats2half2_rn(v.z, v.w);
    uint2 o;
    o.x = *(unsigned int*)&h0;
    o.y = *(unsigned int*)&h1;
    *(uint2*)(g_nbrh + base) = o;
}

// ---------------- k_A: [Pself | Pnbr] = atom_fea @ W[0:128,:] ----------------
#define A_SMEM_BYTES (64*68*8 + 64*256*4)
__global__ __launch_bounds__(256) void k_A(const float* __restrict__ W) {
    extern __shared__ unsigned char smraw[];
    ull*   sA2 = (ull*)smraw;                 // [64 k][68 rows] duplicated pairs
    float* sW  = (float*)(smraw + 64*68*8);   // [64 k][256 cols]
    int tid = threadIdx.x;
    int r0 = blockIdx.x * 64;

    for (int idx = tid; idx < 64*64; idx += 256) {
        int row = idx >> 6, k = idx & 63;
        int r = r0 + row;
        float v = (r < NA) ? g_atom[r*AF + k] : 0.f;
        sA2[k*68 + row] = dup2(v);
    }
    for (int idx = tid; idx < 64*256; idx += 256) {
        int k = idx >> 8, cc = idx & 255;
        sW[idx] = (cc < 128) ? W[k*128 + cc] : W[(k + 64)*128 + (cc - 128)];
    }
    __syncthreads();

    int ct = tid & 15, rt = tid >> 4;
    int c0 = ct * 16;
    ull acc[4][8];
    #pragma unroll
    for (int i = 0; i < 4; i++)
        #pragma unroll
        for (int j = 0; j < 8; j++) acc[i][j] = 0ULL;

    #pragma unroll 1
    for (int k = 0; k < 64; k++) {
        const ulonglong2* ar = (const ulonglong2*)(sA2 + k*68 + rt*4);
        ulonglong2 a01 = ar[0], a23 = ar[1];
        const ulonglong2* wr = (const ulonglong2*)(sW + k*256 + c0);
        ulonglong2 w0 = wr[0], w1 = wr[1], w2 = wr[2], w3 = wr[3];
        ull av[4] = {a01.x, a01.y, a23.x, a23.y};
        ull wv[8] = {w0.x, w0.y, w1.x, w1.y, w2.x, w2.y, w3.x, w3.y};
        #pragma unroll
        for (int i = 0; i < 4; i++)
            #pragma unroll
            for (int j = 0; j < 8; j++)
                ffma2(acc[i][j], av[i], wv[j]);
    }

    bool isSelf = (ct < 8);
    int cb = isSelf ? ct*16 : (ct - 8)*16;
    float* dst = isSelf ? g_Pself : g_Pnbr;
    #pragma unroll
    for (int i = 0; i < 4; i++) {
        int r = r0 + rt*4 + i;
        if (r < NA) {
            float* p = dst + r*C2 + cb;
            float2 f0 = lo2(acc[i][0]), f1 = lo2(acc[i][1]);
            float2 f2 = lo2(acc[i][2]), f3 = lo2(acc[i][3]);
            float2 f4 = lo2(acc[i][4]), f5 = lo2(acc[i][5]);
            float2 f6 = lo2(acc[i][6]), f7 = lo2(acc[i][7]);
            *(float4*)(p)      = make_float4(f0.x, f0.y, f1.x, f1.y);
            *(float4*)(p + 4)  = make_float4(f2.x, f2.y, f3.x, f3.y);
            *(float4*)(p + 8)  = make_float4(f4.x, f4.y, f5.x, f5.y);
            *(float4*)(p + 12) = make_float4(f6.x, f6.y, f7.x, f7.y);
        }
    }
}

// ---------------- k_B: edge GEMM + assemble gated(fp16) + bn1 partial stats ----------------
// block: 128 edge-rows x 128 cols, 256 threads (16 rowtiles x 16 coltiles), thread 8x8
// Row-paired accumulators: A read as natural row-pairs (broadcast), W duplicated
// in conflict-free 10-ull-stride chunks.
#define B_SMEM_A   (41*132*4)              // 21648
#define B_SMEM_W   (41*160*8)              // 52480
#define B_SMEM_BYTES (B_SMEM_A + B_SMEM_W + 16*128*4)   // + sbuf 8192 = 82320
__global__ __launch_bounds__(256, 2) void k_B(const int*   __restrict__ nidx,
                                              const float* __restrict__ Wnf,
                                              const float* __restrict__ bias) {
    extern __shared__ unsigned char smraw[];
    float* sA   = (float*)smraw;                          // [41 k][132 rows]
    ull*   sW2  = (ull*)(smraw + B_SMEM_A);               // [41 k][16 chunks * 10 ull]
    float* sbuf = (float*)(smraw + B_SMEM_A + B_SMEM_W);  // [16][128]
    int tid = threadIdx.x;
    int r0 = blockIdx.x * 128;

    const __half* src = g_nbrh + (size_t)r0 * NFE;   // 128 contiguous rows
    for (int idx = tid; idx < 128*41; idx += 256) {
        int row = idx / 41, k = idx - row*41;
        sA[k*132 + row] = __half2float(src[idx]);
    }
    // W2: chunk c holds cols c*8..c*8+7 duplicated, at [k*160 + c*10 + j]
    for (int idx = tid; idx < 41*128; idx += 256) {
        int k = idx >> 7, cc = idx & 127;
        int c = cc >> 3, j = cc & 7;
        sW2[k*160 + c*10 + j] = dup2(Wnf[k*128 + cc]);
    }
    __syncthreads();

    int ct = tid & 15, rt = tid >> 4;
    int c0 = ct * 8;
    ull acc[4][8];   // [rowpair][col]: lanes = rows 2p, 2p+1
    #pragma unroll
    for (int p = 0; p < 4; p++)
        #pragma unroll
        for (int j = 0; j < 8; j++) acc[p][j] = 0ULL;

    #pragma unroll 1
    for (int k = 0; k < 41; k++) {
        const ulonglong2* ap = (const ulonglong2*)(sA + k*132 + rt*8);
        ulonglong2 a01 = ap[0], a23 = ap[1];   // 8 rows as 4 natural pairs
        ull av[4] = {a01.x, a01.y, a23.x, a23.y};
        const ulonglong2* wp = (const ulonglong2*)(sW2 + k*160 + ct*10);
        ulonglong2 w01 = wp[0], w23 = wp[1], w45 = wp[2], w67 = wp[3];
        ull wv[8] = {w01.x, w01.y, w23.x, w23.y, w45.x, w45.y, w67.x, w67.y};
        #pragma unroll
        for (int p = 0; p < 4; p++)
            #pragma unroll
            for (int j = 0; j < 8; j++)
                ffma2(acc[p][j], av[p], wv[j]);
    }

    float4 bb0 = *(const float4*)(bias + c0);
    float4 bb1 = *(const float4*)(bias + c0 + 4);
    float ssum[8], ssq[8];
    #pragma unroll
    for (int j = 0; j < 8; j++) { ssum[j] = 0.f; ssq[j] = 0.f; }

    int rbase = r0 + rt*8;
    int4 nv0 = *(const int4*)(nidx + rbase);
    int4 nv1 = *(const int4*)(nidx + rbase + 4);
    int jns[8] = {nv0.x, nv0.y, nv0.z, nv0.w, nv1.x, nv1.y, nv1.z, nv1.w};

    #pragma unroll
    for (int i = 0; i < 8; i++) {
        int r = rbase + i;
        int n = r / MN;
        int jn = jns[i];
        const float4 p0 = *(const float4*)(g_Pself + n*C2 + c0);
        const float4 p1 = *(const float4*)(g_Pself + n*C2 + c0 + 4);
        const float4 q0 = *(const float4*)(g_Pnbr + jn*C2 + c0);
        const float4 q1 = *(const float4*)(g_Pnbr + jn*C2 + c0 + 4);
        int p = i >> 1, h = i & 1;
        float av[8];
        #pragma unroll
        for (int j = 0; j < 8; j++) {
            float2 f = lo2(acc[p][j]);
            av[j] = h ? f.y : f.x;
        }
        float gv[8];
        gv[0] = av[0] + p0.x + q0.x + bb0.x;
        gv[1] = av[1] + p0.y + q0.y + bb0.y;
        gv[2] = av[2] + p0.z + q0.z + bb0.z;
        gv[3] = av[3] + p0.w + q0.w + bb0.w;
        gv[4] = av[4] + p1.x + q1.x + bb1.x;
        gv[5] = av[5] + p1.y + q1.y + bb1.y;
        gv[6] = av[6] + p1.z + q1.z + bb1.z;
        gv[7] = av[7] + p1.w + q1.w + bb1.w;
        __half2 h0 = __floats2half2_rn(gv[0], gv[1]);
        __half2 h1 = __floats2half2_rn(gv[2], gv[3]);
        __half2 h2 = __floats2half2_rn(gv[4], gv[5]);
        __half2 h3 = __floats2half2_rn(gv[6], gv[7]);
        uint4 pk;
        pk.x = *(unsigned int*)&h0;
        pk.y = *(unsigned int*)&h1;
        pk.z = *(unsigned int*)&h2;
        pk.w = *(unsigned int*)&h3;
        *(uint4*)(g_gatedh + (size_t)r * C2 + c0) = pk;
        #pragma unroll
        for (int j = 0; j < 8; j++) { ssum[j] += gv[j]; ssq[j] += gv[j]*gv[j]; }
    }

    // deterministic block reduction: 16 rowtiles -> 1, fixed order
    #pragma unroll
    for (int j = 0; j < 8; j++) sbuf[rt*128 + c0 + j] = ssum[j];
    __syncthreads();
    if (tid < 128) {
        float t = 0.f;
        #pragma unroll
        for (int q = 0; q < 16; q++) t += sbuf[q*128 + tid];
        g_part1[tid*NB_B2 + blockIdx.x] = t;
    }
    __syncthreads();
    #pragma unroll
    for (int j = 0; j < 8; j++) sbuf[rt*128 + c0 + j] = ssq[j];
    __syncthreads();
    if (tid < 128) {
        float t = 0.f;
        #pragma unroll
        for (int q = 0; q < 16; q++) t += sbuf[q*128 + tid];
        g_part1[(128 + tid)*NB_B2 + blockIdx.x] = t;
    }
}

// ---------------- k_redcol: deterministic per-column cross-block reduce ----------------
__global__ __launch_bounds__(256) void k_redcol(int which) {
    const float* part = which ? g_part2 : g_part1;
    float* out = which ? g_red2 : g_red1;
    int nb = which ? NB_C : NB_B2;
    int c = blockIdx.x;
    const float* p = part + (size_t)c * nb;
    float a = 0.f;
    for (int i = threadIdx.x; i < nb; i += 256) a += p[i];
    __shared__ float sh[256];
    sh[threadIdx.x] = a;
    __syncthreads();
    for (int s = 128; s > 0; s >>= 1) {
        if (threadIdx.x < s) sh[threadIdx.x] += sh[threadIdx.x + s];
        __syncthreads();
    }
    if (threadIdx.x == 0) out[c] = sh[0];
}

// ---------------- bn finalize ----------------
__global__ void k_fin1(const float* __restrict__ g1, const float* __restrict__ b1) {
    int c = threadIdx.x;   // 128
    const float invn = 1.f / (float)NMROWS;
    float mu  = g_red1[c] * invn;
    float var = g_red1[128 + c] * invn - mu*mu;
    float is  = rsqrtf(var + EPSV);
    float sc  = g1[c] * is;
    g_sc1[c] = sc;
    g_sh1[c] = b1[c] - mu * sc;
}
__global__ void k_fin2(const float* __restrict__ g2, const float* __restrict__ b2) {
    int c = threadIdx.x;   // 64
    const float invn = 1.f / (float)NA;
    float mu  = g_red2[c] * invn;
    float var = g_red2[64 + c] * invn - mu*mu;
    float is  = rsqrtf(var + EPSV);
    float sc  = g2[c] * is;
    g_sc2[c] = sc;
    g_sh2[c] = b2[c] - mu * sc;
}

// ---------------- k_C: BN1 + sigmoid*softplus + sum over m + bn2 partials ----------------
__global__ __launch_bounds__(256) void k_C() {
    int tid = threadIdx.x;
    int f = tid & 63, ag = tid >> 6;
    int n0 = blockIdx.x * 16;
    float sc0 = g_sc1[f],      sh0 = g_sh1[f];
    float sc1 = g_sc1[64 + f], sh1 = g_sh1[64 + f];
    float ps = 0.f, pq = 0.f;
    __shared__ float st[512];
    #pragma unroll
    for (int aa = 0; aa < 4; aa++) {
        int n = n0 + ag*4 + aa;
        const __half* gp = g_gatedh + (size_t)n * MN * C2;
        float s = 0.f;
        #pragma unroll
        for (int m = 0; m < MN; m++) {
            float y0 = __half2float(gp[m*C2 + f])      * sc0 + sh0;
            float y1 = __half2float(gp[m*C2 + 64 + f]) * sc1 + sh1;
            s += sigmoidf_(y0) * softplusf(y1);
        }
        g_summed[n*AF + f] = s;
        ps += s; pq += s*s;
    }
    st[ag*64 + f] = ps;
    st[256 + ag*64 + f] = pq;
    __syncthreads();
    if (tid < 128) {
        int w = tid >> 6, f2 = tid & 63;
        float t = 0.f;
        #pragma unroll
        for (int q = 0; q < 4; q++) t += st[w*256 + q*64 + f2];
        g_part2[(w*64 + f2)*NB_C + blockIdx.x] = t;
    }
}

// ---------------- k_update: atom = softplus(atom + bn2(summed)) ----------------
__global__ __launch_bounds__(256) void k_update() {
    int i = blockIdx.x * 256 + threadIdx.x;
    int base = i * 4;
    int c = base & 63;
    float4 a = *(const float4*)(g_atom + base);
    float4 s = *(const float4*)(g_summed + base);
    float4 sc = *(const float4*)(g_sc2 + c);
    float4 sh = *(const float4*)(g_sh2 + c);
    float4 o;
    o.x = softplusf(a.x + s.x*sc.x + sh.x);
    o.y = softplusf(a.y + s.y*sc.y + sh.y);
    o.z = softplusf(a.z + s.z*sc.z + sh.z);
    o.w = softplusf(a.w + s.w*sc.w + sh.w);
    *(float4*)(g_atom + base) = o;
}

// ---------------- k_head: pooling + softplus + FC + softplus + out ----------------
__global__ __launch_bounds__(128) void k_head(const int* __restrict__ cidx,
                                              const float* __restrict__ Wfc,
                                              const float* __restrict__ bfc,
                                              const float* __restrict__ Wout,
                                              const float* __restrict__ bout,
                                              float* __restrict__ out) {
    __shared__ float s_c[64];
    __shared__ float s_h[128];
    __shared__ float s_red[128];
    int b = blockIdx.x, t = threadIdx.x;
    int f = t & 63, half = t >> 6;
    const int* ci = cidx + b * APC;
    float acc = 0.f;
    for (int a = half*500; a < half*500 + 500; a++)
        acc += g_atom[ci[a]*AF + f];
    s_red[t] = acc;
    __syncthreads();
    if (t < 64) {
        float m = (s_red[t] + s_red[t + 64]) * (1.f / (float)APC);
        s_c[t] = softplusf(m);
    }
    __syncthreads();
    {
        float a2 = bfc[t];
        #pragma unroll 8
        for (int f2 = 0; f2 < 64; f2++) a2 += s_c[f2] * Wfc[f2*HFD + t];
        s_h[t] = softplusf(a2);
    }
    __syncthreads();
    if (t < 64) {
        float a3 = bout[t];
        #pragma unroll 8
        for (int h = 0; h < 128; h++) a3 += s_h[h] * Wout[h*HIDD + t];
        out[b*HIDD + t] = a3;
    }
}

// ---------------- launch ----------------
extern "C" void kernel_launch(void* const* d_in, const int* in_sizes, int n_in,
                              void* d_out, int out_size) {
    const int*   atom_num = (const int*)  d_in[0];
    const float* nbr_fea  = (const float*)d_in[1];
    const int*   nbr_idx  = (const int*)  d_in[2];
    const int*   cidx     = (const int*)  d_in[3];
    const float* emb      = (const float*)d_in[4];
    const float* W_full   = (const float*)d_in[5];
    const float* b_full   = (const float*)d_in[6];
    const float* bn1g     = (const float*)d_in[7];
    const float* bn1b     = (const float*)d_in[8];
    const float* bn2g     = (const float*)d_in[9];
    const float* bn2b     = (const float*)d_in[10];
    const float* W_fc     = (const float*)d_in[11];
    const float* b_fc     = (const float*)d_in[12];
    const float* W_out    = (const float*)d_in[13];
    const float* b_out    = (const float*)d_in[14];
    float* out = (float*)d_out;

    cudaFuncSetAttribute(k_A, cudaFuncAttributeMaxDynamicSharedMemorySize, A_SMEM_BYTES);
    cudaFuncSetAttribute(k_B, cudaFuncAttributeMaxDynamicSharedMemorySize, B_SMEM_BYTES);

    k_embed<<<NA*AF/1024, 256>>>(atom_num, emb);
    k_prep<<<(NBR_ELEMS/4 + 255)/256, 256>>>(nbr_fea);

    for (int l = 0; l < 3; l++) {
        const float* W = W_full + l * 169 * 128;
        k_A<<<(NA + 63)/64, 256, A_SMEM_BYTES>>>(W);
        k_B<<<NB_B2, 256, B_SMEM_BYTES>>>(nbr_idx, W + 128*128, b_full + l*128);
        k_redcol<<<256, 256>>>(0);
        k_fin1<<<1, 128>>>(bn1g + l*128, bn1b + l*128);
        k_C<<<NB_C, 256>>>();
        k_redcol<<<128, 256>>>(1);
        k_fin2<<<1, 64>>>(bn2g + l*64, bn2b + l*64);
        k_update<<<NA*AF/1024, 256>>>();
    }
    k_head<<<N0C, 128>>>(cidx, W_fc, b_fc, W_out, b_out, out);
}

// round 13
// speedup vs baseline: 1.9892x; 1.5303x over previous
#include <cuda_runtime.h>
#include <cuda_fp16.h>
#include <cuda_bf16.h>
#include <cstdint>
#include <cstddef>

// ---------------- problem constants ----------------
#define NA      100000          // atoms
#define MN      12              // neighbors
#define AF      64              // atom feature len
#define NFE     41              // nbr feature len
#define C2      128             // 2*AF
#define NMROWS  (NA*MN)         // 1,200,000 edge rows
#define NB_B2   (NMROWS/128)    // 9375 blocks in gemm pass (128 rows/block)
#define NB_C    (NA/16)         // 6250 blocks in apply pass
#define N0C     100             // crystals
#define APC     1000            // atoms per crystal
#define HFD     128
#define HIDD    64
#define EPSV    1e-5f
#define NBR_ELEMS (NMROWS*NFE)  // 49,200,000

typedef unsigned long long ull;

// ---------------- device scratch (no allocations allowed) ----------------
__device__ float  g_atom  [NA*AF];
__device__ float  g_Pself [NA*C2];
__device__ float  g_Pnbr  [NA*C2];
__device__ __half g_gatedh[(size_t)NMROWS*C2];   // 307 MB
__device__ __half g_nbrh  [NBR_ELEMS];           // 98 MB fp16 copy of nbr_fea
__device__ float  g_summed[NA*AF];
__device__ float  g_part1 [256*NB_B2];
__device__ float  g_part2 [128*NB_C];
__device__ float  g_red1  [256];
__device__ float  g_red2  [128];
__device__ float  g_sc1[128], g_sh1[128];
__device__ float  g_sc2[64],  g_sh2[64];

// ---------------- helpers ----------------
__device__ __forceinline__ float softplusf(float x) {
    return fmaxf(x, 0.f) + log1pf(__expf(-fabsf(x)));
}
// fast variants for the bulk k_C pass (error ~1e-6 rel, budget 1e-3)
__device__ __forceinline__ float fsig(float x) {
    return __fdividef(1.f, 1.f + __expf(-x));
}
__device__ __forceinline__ float fsp(float x) {
    return fmaxf(x, 0.f) + __logf(1.f + __expf(-fabsf(x)));
}
__device__ __forceinline__ float sigmoidf_(float x) {
    return 1.f / (1.f + __expf(-x));
}
// packed f32x2 FMA: d = a*b + d  (two fp32 lanes per issue slot)
__device__ __forceinline__ void ffma2(ull& d, ull a, ull b) {
    asm("fma.rn.f32x2 %0, %1, %2, %0;" : "+l"(d) : "l"(a), "l"(b));
}
__device__ __forceinline__ ull dup2(float v) {
    unsigned int u = __float_as_uint(v);
    ull r;
    asm("mov.b64 %0, {%1, %1};" : "=l"(r) : "r"(u));
    return r;
}
__device__ __forceinline__ float2 lo2(const ull& v) {
    return *reinterpret_cast<const float2*>(&v);
}

// ---------------- k_embed ----------------
__global__ __launch_bounds__(256) void k_embed(const int* __restrict__ atom_num,
                                               const float* __restrict__ emb) {
    int i = blockIdx.x * 256 + threadIdx.x;
    int base = i * 4;
    int n = base >> 6;
    int c = base & 63;
    int a = atom_num[n];
    float4 v = *(const float4*)(emb + a * AF + c);
    *(float4*)(g_atom + base) = v;
}

// ---------------- k_prep: nbr_fea fp32 -> fp16 (once) ----------------
__global__ __launch_bounds__(256) void k_prep(const float* __restrict__ nbrF) {
    int i = blockIdx.x * 256 + threadIdx.x;
    int base = i * 4;
    if (base >= NBR_ELEMS) return;
    float4 v = *(const float4*)(nbrF + base);
    __half2 h0 = __floats2half2_rn(v.x, v.y);
    __half2 h1 = __floats2half2_rn(v.z, v.w);
    uint2 o;
    o.x = *(unsigned int*)&h0;
    o.y = *(unsigned int*)&h1;
    *(uint2*)(g_nbrh + base) = o;
}

// ---------------- k_A2: Pself/Pnbr = atom_fea @ Wslab ----------------
// block: 128 rows x 128 cols, 256 threads (16 rt x 16 ct), thread 8x8.
// blockIdx.y: 0 -> Pself (W rows 0..63), 1 -> Pnbr (W rows 64..127).
// Column-paired accumulators; W natural in conflict-free 12-float-stride chunks;
// A natural (broadcast) + register dup.
#define A2_SMEM_A  (64*132*4)              // 33792
#define A2_SMEM_W  (64*192*4)              // 49152
#define A2_SMEM_BYTES (A2_SMEM_A + A2_SMEM_W)   // 82944
__global__ __launch_bounds__(256, 2) void k_A2(const float* __restrict__ W) {
    extern __shared__ unsigned char smraw[];
    float* sA = (float*)smraw;                  // [64 k][132 rows]
    float* sW = (float*)(smraw + A2_SMEM_A);    // [64 k][16 chunks * 12 floats]
    int tid = threadIdx.x;
    int r0 = blockIdx.x * 128;
    int half = blockIdx.y;
    const float* Wslab = W + half * 64 * 128;

    for (int idx = tid; idx < 128*64; idx += 256) {
        int row = idx >> 6, k = idx & 63;
        int r = r0 + row;
        sA[k*132 + row] = (r < NA) ? g_atom[r*AF + k] : 0.f;
    }
    for (int idx = tid; idx < 64*128; idx += 256) {
        int k = idx >> 7, cc = idx & 127;
        int c = cc >> 3, j = cc & 7;
        sW[k*192 + c*12 + j] = Wslab[k*128 + cc];
    }
    __syncthreads();

    int ct = tid & 15, rt = tid >> 4;
    int c0 = ct * 8;
    ull acc[8][4];   // [row][colpair]: lanes = cols c0+2j, c0+2j+1
    #pragma unroll
    for (int i = 0; i < 8; i++)
        #pragma unroll
        for (int j = 0; j < 4; j++) acc[i][j] = 0ULL;

    #pragma unroll 1
    for (int k = 0; k < 64; k++) {
        const float4* ap = (const float4*)(sA + k*132 + rt*8);
        float4 a03 = ap[0], a47 = ap[1];
        ull ad[8] = {dup2(a03.x), dup2(a03.y), dup2(a03.z), dup2(a03.w),
                     dup2(a47.x), dup2(a47.y), dup2(a47.z), dup2(a47.w)};
        const ulonglong2* wp = (const ulonglong2*)(sW + k*192 + ct*12);
        ulonglong2 wA = wp[0], wB = wp[1];
        ull wv[4] = {wA.x, wA.y, wB.x, wB.y};
        #pragma unroll
        for (int i = 0; i < 8; i++)
            #pragma unroll
            for (int j = 0; j < 4; j++)
                ffma2(acc[i][j], ad[i], wv[j]);
    }

    float* dst = half ? g_Pnbr : g_Pself;
    #pragma unroll
    for (int i = 0; i < 8; i++) {
        int r = r0 + rt*8 + i;
        if (r < NA) {
            float2 f0 = lo2(acc[i][0]), f1 = lo2(acc[i][1]);
            float2 f2 = lo2(acc[i][2]), f3 = lo2(acc[i][3]);
            float* p = dst + r*C2 + c0;
            *(float4*)(p)     = make_float4(f0.x, f0.y, f1.x, f1.y);
            *(float4*)(p + 4) = make_float4(f2.x, f2.y, f3.x, f3.y);
        }
    }
}

// ---------------- k_B: edge GEMM + assemble gated(fp16) + bn1 partial stats ----------------
// block: 128 edge-rows x 128 cols, 256 threads, thread 8x8.
// Column-paired accumulators; W natural conflict-free chunks; A broadcast + reg dup.
#define B_SMEM_A   (41*132*4)              // 21648
#define B_SMEM_W   (41*192*4)              // 31488
#define B_SMEM_BYTES (B_SMEM_A + B_SMEM_W + 16*128*4)   // + sbuf 8192 = 61328
__global__ __launch_bounds__(256, 2) void k_B(const int*   __restrict__ nidx,
                                              const float* __restrict__ Wnf,
                                              const float* __restrict__ bias) {
    extern __shared__ unsigned char smraw[];
    float* sA   = (float*)smraw;                          // [41 k][132 rows]
    float* sW   = (float*)(smraw + B_SMEM_A);             // [41 k][16 chunks * 12]
    float* sbuf = (float*)(smraw + B_SMEM_A + B_SMEM_W);  // [16][128]
    int tid = threadIdx.x;
    int r0 = blockIdx.x * 128;

    const __half* src = g_nbrh + (size_t)r0 * NFE;   // 128 contiguous rows
    for (int idx = tid; idx < 128*41; idx += 256) {
        int row = idx / 41, k = idx - row*41;
        sA[k*132 + row] = __half2float(src[idx]);
    }
    for (int idx = tid; idx < 41*128; idx += 256) {
        int k = idx >> 7, cc = idx & 127;
        int c = cc >> 3, j = cc & 7;
        sW[k*192 + c*12 + j] = Wnf[k*128 + cc];
    }
    __syncthreads();

    int ct = tid & 15, rt = tid >> 4;
    int c0 = ct * 8;
    ull acc[8][4];   // [row][colpair]
    #pragma unroll
    for (int i = 0; i < 8; i++)
        #pragma unroll
        for (int j = 0; j < 4; j++) acc[i][j] = 0ULL;

    #pragma unroll 1
    for (int k = 0; k < 41; k++) {
        const float4* ap = (const float4*)(sA + k*132 + rt*8);
        float4 a03 = ap[0], a47 = ap[1];
        ull ad[8] = {dup2(a03.x), dup2(a03.y), dup2(a03.z), dup2(a03.w),
                     dup2(a47.x), dup2(a47.y), dup2(a47.z), dup2(a47.w)};
        const ulonglong2* wp = (const ulonglong2*)(sW + k*192 + ct*12);
        ulonglong2 wA = wp[0], wB = wp[1];
        ull wv[4] = {wA.x, wA.y, wB.x, wB.y};
        #pragma unroll
        for (int i = 0; i < 8; i++)
            #pragma unroll
            for (int j = 0; j < 4; j++)
                ffma2(acc[i][j], ad[i], wv[j]);
    }

    float4 bb0 = *(const float4*)(bias + c0);
    float4 bb1 = *(const float4*)(bias + c0 + 4);
    float ssum[8], ssq[8];
    #pragma unroll
    for (int j = 0; j < 8; j++) { ssum[j] = 0.f; ssq[j] = 0.f; }

    int rbase = r0 + rt*8;
    int4 nv0 = *(const int4*)(nidx + rbase);
    int4 nv1 = *(const int4*)(nidx + rbase + 4);
    int jns[8] = {nv0.x, nv0.y, nv0.z, nv0.w, nv1.x, nv1.y, nv1.z, nv1.w};

    #pragma unroll
    for (int i = 0; i < 8; i++) {
        int r = rbase + i;
        int n = r / MN;
        int jn = jns[i];
        const float4 p0 = *(const float4*)(g_Pself + n*C2 + c0);
        const float4 p1 = *(const float4*)(g_Pself + n*C2 + c0 + 4);
        const float4 q0 = *(const float4*)(g_Pnbr + jn*C2 + c0);
        const float4 q1 = *(const float4*)(g_Pnbr + jn*C2 + c0 + 4);
        float2 f0 = lo2(acc[i][0]), f1 = lo2(acc[i][1]);
        float2 f2 = lo2(acc[i][2]), f3 = lo2(acc[i][3]);
        float gv[8];
        gv[0] = f0.x + p0.x + q0.x + bb0.x;
        gv[1] = f0.y + p0.y + q0.y + bb0.y;
        gv[2] = f1.x + p0.z + q0.z + bb0.z;
        gv[3] = f1.y + p0.w + q0.w + bb0.w;
        gv[4] = f2.x + p1.x + q1.x + bb1.x;
        gv[5] = f2.y + p1.y + q1.y + bb1.y;
        gv[6] = f3.x + p1.z + q1.z + bb1.z;
        gv[7] = f3.y + p1.w + q1.w + bb1.w;
        __half2 h0 = __floats2half2_rn(gv[0], gv[1]);
        __half2 h1 = __floats2half2_rn(gv[2], gv[3]);
        __half2 h2 = __floats2half2_rn(gv[4], gv[5]);
        __half2 h3 = __floats2half2_rn(gv[6], gv[7]);
        uint4 pk;
        pk.x = *(unsigned int*)&h0;
        pk.y = *(unsigned int*)&h1;
        pk.z = *(unsigned int*)&h2;
        pk.w = *(unsigned int*)&h3;
        *(uint4*)(g_gatedh + (size_t)r * C2 + c0) = pk;
        #pragma unroll
        for (int j = 0; j < 8; j++) { ssum[j] += gv[j]; ssq[j] += gv[j]*gv[j]; }
    }

    // deterministic block reduction: 16 rowtiles -> 1, fixed order
    #pragma unroll
    for (int j = 0; j < 8; j++) sbuf[rt*128 + c0 + j] = ssum[j];
    __syncthreads();
    if (tid < 128) {
        float t = 0.f;
        #pragma unroll
        for (int q = 0; q < 16; q++) t += sbuf[q*128 + tid];
        g_part1[tid*NB_B2 + blockIdx.x] = t;
    }
    __syncthreads();
    #pragma unroll
    for (int j = 0; j < 8; j++) sbuf[rt*128 + c0 + j] = ssq[j];
    __syncthreads();
    if (tid < 128) {
        float t = 0.f;
        #pragma unroll
        for (int q = 0; q < 16; q++) t += sbuf[q*128 + tid];
        g_part1[(128 + tid)*NB_B2 + blockIdx.x] = t;
    }
}

// ---------------- k_redcol: deterministic per-column cross-block reduce ----------------
__global__ __launch_bounds__(256) void k_redcol(int which) {
    const float* part = which ? g_part2 : g_part1;
    float* out = which ? g_red2 : g_red1;
    int nb = which ? NB_C : NB_B2;
    int c = blockIdx.x;
    const float* p = part + (size_t)c * nb;
    float a = 0.f;
    for (int i = threadIdx.x; i < nb; i += 256) a += p[i];
    __shared__ float sh[256];
    sh[threadIdx.x] = a;
    __syncthreads();
    for (int s = 128; s > 0; s >>= 1) {
        if (threadIdx.x < s) sh[threadIdx.x] += sh[threadIdx.x + s];
        __syncthreads();
    }
    if (threadIdx.x == 0) out[c] = sh[0];
}

// ---------------- bn finalize ----------------
__global__ void k_fin1(const float* __restrict__ g1, const float* __restrict__ b1) {
    int c = threadIdx.x;   // 128
    const float invn = 1.f / (float)NMROWS;
    float mu  = g_red1[c] * invn;
    float var = g_red1[128 + c] * invn - mu*mu;
    float is  = rsqrtf(var + EPSV);
    float sc  = g1[c] * is;
    g_sc1[c] = sc;
    g_sh1[c] = b1[c] - mu * sc;
}
__global__ void k_fin2(const float* __restrict__ g2, const float* __restrict__ b2) {
    int c = threadIdx.x;   // 64
    const float invn = 1.f / (float)NA;
    float mu  = g_red2[c] * invn;
    float var = g_red2[64 + c] * invn - mu*mu;
    float is  = rsqrtf(var + EPSV);
    float sc  = g2[c] * is;
    g_sc2[c] = sc;
    g_sh2[c] = b2[c] - mu * sc;
}

// ---------------- k_C: BN1 + sigmoid*softplus + sum over m + bn2 partials ----------------
// block: 16 atoms, 256 threads = 8 atom-groups (2 atoms each) x 32 f-pairs.
// half2 loads (coalesced 128B/warp), float2 stores, fast transcendentals.
__global__ __launch_bounds__(256) void k_C() {
    int tid = threadIdx.x;
    int fp = tid & 31;          // f-pair index: covers f = 2fp, 2fp+1
    int ag = tid >> 5;          // 0..7
    int n0 = blockIdx.x * 16;
    int f0 = fp * 2;
    float sc0a = g_sc1[f0],     sc0b = g_sc1[f0+1];
    float sh0a = g_sh1[f0],     sh0b = g_sh1[f0+1];
    float sc1a = g_sc1[64+f0],  sc1b = g_sc1[64+f0+1];
    float sh1a = g_sh1[64+f0],  sh1b = g_sh1[64+f0+1];
    float ps0 = 0.f, ps1 = 0.f, pq0 = 0.f, pq1 = 0.f;
    __shared__ float st[1024];
    #pragma unroll
    for (int aa = 0; aa < 2; aa++) {
        int n = n0 + ag*2 + aa;
        const __half* gp = g_gatedh + (size_t)n * MN * C2;
        float s0 = 0.f, s1 = 0.f;
        #pragma unroll
        for (int m = 0; m < MN; m++) {
            __half2 u0 = *(const __half2*)(gp + m*C2 + f0);
            __half2 u1 = *(const __half2*)(gp + m*C2 + 64 + f0);
            float2 x0 = __half22float2(u0);
            float2 x1 = __half22float2(u1);
            float ya = x0.x*sc0a + sh0a, yb = x0.y*sc0b + sh0b;
            float za = x1.x*sc1a + sh1a, zb = x1.y*sc1b + sh1b;
            s0 += fsig(ya) * fsp(za);
            s1 += fsig(yb) * fsp(zb);
        }
        *(float2*)(g_summed + n*AF + f0) = make_float2(s0, s1);
        ps0 += s0; pq0 += s0*s0;
        ps1 += s1; pq1 += s1*s1;
    }
    st[ag*64 + f0]       = ps0;
    st[ag*64 + f0 + 1]   = ps1;
    st[512 + ag*64 + f0]     = pq0;
    st[512 + ag*64 + f0 + 1] = pq1;
    __syncthreads();
    if (tid < 128) {
        int w = tid >> 6, f2 = tid & 63;
        float t = 0.f;
        #pragma unroll
        for (int q = 0; q < 8; q++) t += st[w*512 + q*64 + f2];
        g_part2[(w*64 + f2)*NB_C + blockIdx.x] = t;
    }
}

// ---------------- k_update: atom = softplus(atom + bn2(summed)) ----------------
__global__ __launch_bounds__(256) void k_update() {
    int i = blockIdx.x * 256 + threadIdx.x;
    int base = i * 4;
    int c = base & 63;
    float4 a = *(const float4*)(g_atom + base);
    float4 s = *(const float4*)(g_summed + base);
    float4 sc = *(const float4*)(g_sc2 + c);
    float4 sh = *(const float4*)(g_sh2 + c);
    float4 o;
    o.x = softplusf(a.x + s.x*sc.x + sh.x);
    o.y = softplusf(a.y + s.y*sc.y + sh.y);
    o.z = softplusf(a.z + s.z*sc.z + sh.z);
    o.w = softplusf(a.w + s.w*sc.w + sh.w);
    *(float4*)(g_atom + base) = o;
}

// ---------------- k_head: pooling + softplus + FC + softplus + out ----------------
__global__ __launch_bounds__(128) void k_head(const int* __restrict__ cidx,
                                              const float* __restrict__ Wfc,
                                              const float* __restrict__ bfc,
                                              const float* __restrict__ Wout,
                                              const float* __restrict__ bout,
                                              float* __restrict__ out) {
    __shared__ float s_c[64];
    __shared__ float s_h[128];
    __shared__ float s_red[128];
    int b = blockIdx.x, t = threadIdx.x;
    int f = t & 63, half = t >> 6;
    const int* ci = cidx + b * APC;
    float acc = 0.f;
    for (int a = half*500; a < half*500 + 500; a++)
        acc += g_atom[ci[a]*AF + f];
    s_red[t] = acc;
    __syncthreads();
    if (t < 64) {
        float m = (s_red[t] + s_red[t + 64]) * (1.f / (float)APC);
        s_c[t] = softplusf(m);
    }
    __syncthreads();
    {
        float a2 = bfc[t];
        #pragma unroll 8
        for (int f2 = 0; f2 < 64; f2++) a2 += s_c[f2] * Wfc[f2*HFD + t];
        s_h[t] = softplusf(a2);
    }
    __syncthreads();
    if (t < 64) {
        float a3 = bout[t];
        #pragma unroll 8
        for (int h = 0; h < 128; h++) a3 += s_h[h] * Wout[h*HIDD + t];
        out[b*HIDD + t] = a3;
    }
}

// ---------------- launch ----------------
extern "C" void kernel_launch(void* const* d_in, const int* in_sizes, int n_in,
                              void* d_out, int out_size) {
    const int*   atom_num = (const int*)  d_in[0];
    const float* nbr_fea  = (const float*)d_in[1];
    const int*   nbr_idx  = (const int*)  d_in[2];
    const int*   cidx     = (const int*)  d_in[3];
    const float* emb      = (const float*)d_in[4];
    const float* W_full   = (const float*)d_in[5];
    const float* b_full   = (const float*)d_in[6];
    const float* bn1g     = (const float*)d_in[7];
    const float* bn1b     = (const float*)d_in[8];
    const float* bn2g     = (const float*)d_in[9];
    const float* bn2b     = (const float*)d_in[10];
    const float* W_fc     = (const float*)d_in[11];
    const float* b_fc     = (const float*)d_in[12];
    const float* W_out    = (const float*)d_in[13];
    const float* b_out    = (const float*)d_in[14];
    float* out = (float*)d_out;

    cudaFuncSetAttribute(k_A2, cudaFuncAttributeMaxDynamicSharedMemorySize, A2_SMEM_BYTES);
    cudaFuncSetAttribute(k_B,  cudaFuncAttributeMaxDynamicSharedMemorySize, B_SMEM_BYTES);

    k_embed<<<NA*AF/1024, 256>>>(atom_num, emb);
    k_prep<<<(NBR_ELEMS/4 + 255)/256, 256>>>(nbr_fea);

    for (int l = 0; l < 3; l++) {
        const float* W = W_full + l * 169 * 128;
        k_A2<<<dim3((NA + 127)/128, 2), 256, A2_SMEM_BYTES>>>(W);
        k_B<<<NB_B2, 256, B_SMEM_BYTES>>>(nbr_idx, W + 128*128, b_full + l*128);
        k_redcol<<<256, 256>>>(0);
        k_fin1<<<1, 128>>>(bn1g + l*128, bn1b + l*128);
        k_C<<<NB_C, 256>>>();
        k_redcol<<<128, 256>>>(1);
        k_fin2<<<1, 64>>>(bn2g + l*64, bn2b + l*64);
        k_update<<<NA*AF/1024, 256>>>();
    }
    k_head<<<N0C, 128>>>(cidx, W_fc, b_fc, W_out, b_out, out);
}